// round 1
// baseline (speedup 1.0000x reference)
#include <cuda_runtime.h>

#define N_NODES 50000
#define N_EDGES 800000
#define NS (N_NODES * 4)   // node-sample rows

// ---------------- scratch (module globals; no runtime allocation) ----------------
__device__ __align__(16) float4 g_hf [N_NODES * 24];   // [N][96] as float4
__device__ __align__(16) float4 g_agg[N_NODES * 24];   // [N][96] as float4
__device__ float g_stats[1200];                        // 2 paths x (24x25): Gram + col-sum
__device__ float g_W1f[2][24 * 64];                    // BN-folded W1 (0=shared,1=agg)
__device__ float g_b1f[2][64];
__device__ float g_ma [N_NODES * 64];                  // aggregated-path output

// ---------------- packed f32x2 helpers (Blackwell FFMA2) ----------------
typedef unsigned long long u64;
__device__ __forceinline__ u64 dup2(float v) {
    u64 r; asm("mov.b64 %0, {%1,%1};" : "=l"(r) : "f"(v)); return r;
}
__device__ __forceinline__ void fma2(u64 &d, u64 a, u64 b) {
    asm("fma.rn.f32x2 %0, %1, %2, %3;" : "=l"(d) : "l"(a), "l"(b), "l"(d));
}
__device__ __forceinline__ void unpack2(u64 v, float &lo, float &hi) {
    asm("mov.b64 {%0,%1}, %2;" : "=f"(lo), "=f"(hi) : "l"(v));
}

// ================= K1: build hf = concat(x, c), zero agg + stats =================
__global__ void k_build(const float* __restrict__ x, const float* __restrict__ c) {
    int tid = blockIdx.x * blockDim.x + threadIdx.x;
    if (tid < 1200) g_stats[tid] = 0.f;
    if (tid >= NS) return;
    int n = tid >> 2, s = tid & 3;
    const float4* x4 = reinterpret_cast<const float4*>(x) + n * 4;
    const float4* c4 = reinterpret_cast<const float4*>(c) + (n * 4 + s) * 2;
    float4* dst = g_hf + n * 24 + s * 6;
    dst[0] = x4[0]; dst[1] = x4[1]; dst[2] = x4[2]; dst[3] = x4[3];
    dst[4] = c4[0]; dst[5] = c4[1];
    float4 z = make_float4(0.f, 0.f, 0.f, 0.f);
    float4* ag = g_agg + n * 24 + s * 6;
    ag[0] = z; ag[1] = z; ag[2] = z; ag[3] = z; ag[4] = z; ag[5] = z;
}

// ================= K2: edge scatter-add (8 threads/edge, v4 float reds) ==========
__global__ void k_scatter(const int* __restrict__ ei) {
    unsigned tid = blockIdx.x * blockDim.x + threadIdx.x;
    unsigned e = tid >> 3;
    if (e >= N_EDGES) return;
    unsigned q = tid & 7;
    int src = __ldg(ei + e);
    int dst = __ldg(ei + N_EDGES + e);
    const float4* srow = g_hf + src * 24;
    float4* drow = g_agg + dst * 24;
#pragma unroll
    for (int i = 0; i < 3; i++) {
        unsigned idx = q + 8u * i;
        float4 v = srow[idx];
        asm volatile("red.global.add.v4.f32 [%0], {%1,%2,%3,%4};"
                     :: "l"(drow + idx), "f"(v.x), "f"(v.y), "f"(v.z), "f"(v.w)
                     : "memory");
    }
}

// ================= K3: per-block partial Gram/mean stats for both BN paths =======
__global__ void __launch_bounds__(128) k_stats(const float* __restrict__ eps_s_p,
                                               const float* __restrict__ eps_a_p) {
    __shared__ float sm_m[128][25];  // shared-path rows (32 nodes x 4 samples)
    __shared__ float sm_t[128][25];  // agg-eps rows (temp)
    __shared__ float sm_a[32][25];   // agg-path rows (per node)
    const float es = 1.f + *eps_s_p;
    const float ea = 1.f + *eps_a_p;
    int tid = threadIdx.x;
    int n = blockIdx.x * 32 + (tid >> 2);
    int s = tid & 3;
    if (n < N_NODES) {
        const float4* h4 = g_hf  + n * 24 + s * 6;
        const float4* a4 = g_agg + n * 24 + s * 6;
#pragma unroll
        for (int q = 0; q < 6; q++) {
            float4 h = h4[q], a = a4[q];
            sm_m[tid][q*4+0] = es*h.x + a.x;  sm_t[tid][q*4+0] = ea*h.x + a.x;
            sm_m[tid][q*4+1] = es*h.y + a.y;  sm_t[tid][q*4+1] = ea*h.y + a.y;
            sm_m[tid][q*4+2] = es*h.z + a.z;  sm_t[tid][q*4+2] = ea*h.z + a.z;
            sm_m[tid][q*4+3] = es*h.w + a.w;  sm_t[tid][q*4+3] = ea*h.w + a.w;
        }
    } else {
#pragma unroll
        for (int j = 0; j < 24; j++) { sm_m[tid][j] = 0.f; sm_t[tid][j] = 0.f; }
    }
    __syncthreads();
    for (int it = tid; it < 32 * 24; it += 128) {
        int nl = it / 24, j = it % 24;
        sm_a[nl][j] = 0.25f * (sm_t[nl*4][j] + sm_t[nl*4+1][j] +
                               sm_t[nl*4+2][j] + sm_t[nl*4+3][j]);
    }
    __syncthreads();
    for (int item = tid; item < 1200; item += 128) {
        int path = item / 600;
        int r6 = item % 600;
        int j = r6 / 25, k = r6 % 25;
        float acc = 0.f;
        if (path == 0) {
            if (k < 24) { for (int r = 0; r < 128; r++) acc += sm_m[r][j] * sm_m[r][k]; }
            else        { for (int r = 0; r < 128; r++) acc += sm_m[r][j]; }
        } else {
            if (k < 24) { for (int r = 0; r < 32; r++) acc += sm_a[r][j] * sm_a[r][k]; }
            else        { for (int r = 0; r < 32; r++) acc += sm_a[r][j]; }
        }
        atomicAdd(&g_stats[item], acc);
    }
}

// ================= K4: fold BN analytically into W1/b1 ===========================
__global__ void k_fold(const float* __restrict__ W1s, const float* __restrict__ b1s,
                       const float* __restrict__ g1s, const float* __restrict__ be1s,
                       const float* __restrict__ W1a, const float* __restrict__ b1a,
                       const float* __restrict__ g1a, const float* __restrict__ be1a) {
    int t = threadIdx.x;
    if (t >= 128) return;
    int path = t >> 6, cc = t & 63;
    const float* W1 = path ? W1a : W1s;
    const float* b1 = path ? b1a : b1s;
    const float* g1 = path ? g1a : g1s;
    const float* be = path ? be1a : be1s;
    float invR = path ? (1.f / 50000.f) : (1.f / 200000.f);
    const float* St = g_stats + path * 600;
    float mean[24], wc[24];
    float mu = b1[cc];
#pragma unroll
    for (int j = 0; j < 24; j++) {
        mean[j] = St[j * 25 + 24] * invR;
        wc[j] = W1[j * 64 + cc];
        mu += mean[j] * wc[j];
    }
    float var = 0.f;
    for (int j = 0; j < 24; j++) {
#pragma unroll
        for (int k = 0; k < 24; k++) {
            var += (St[j * 25 + k] * invR - mean[j] * mean[k]) * wc[j] * wc[k];
        }
    }
    float alpha = g1[cc] * rsqrtf(var + 1e-5f);
#pragma unroll
    for (int j = 0; j < 24; j++) g_W1f[path][j * 64 + cc] = wc[j] * alpha;
    g_b1f[path][cc] = alpha * (b1[cc] - mu) + be[cc];
}

// ================= K5a: aggregated-path MLP -> g_ma ==============================
__global__ void __launch_bounds__(256) k_agg(const float* __restrict__ W2a,
                                             const float* __restrict__ b2a,
                                             const float* __restrict__ eps_a_p) {
    __shared__ u64 w1p[24][32];
    __shared__ u64 b1p[32];
    __shared__ u64 w2p[64][32];
    __shared__ u64 b2p[32];
    __shared__ float ar[8][24];
    __shared__ float tmp[8][4][24];
    __shared__ float hsm[8][64];
    int tid = threadIdx.x;
    for (int i = tid; i < 24 * 64; i += 256) {
        int j = i >> 6, l = i & 63;
        ((float*)&w1p[j][l & 31])[l >> 5] = g_W1f[1][i];
    }
    for (int i = tid; i < 64 * 64; i += 256) {
        int k = i >> 6, l = i & 63;
        ((float*)&w2p[k][l & 31])[l >> 5] = W2a[i];
    }
    if (tid < 64) {
        ((float*)&b1p[tid & 31])[tid >> 5] = g_b1f[1][tid];
        ((float*)&b2p[tid & 31])[tid >> 5] = b2a[tid];
    }
    float ea = 1.f + *eps_a_p;
    __syncthreads();
    int w = tid >> 5, lane = tid & 31;
    for (int n = blockIdx.x * 8 + w; n < N_NODES; n += gridDim.x * 8) {
        __syncwarp();
        if (lane < 24) {
            int s = lane / 6, q = lane % 6;
            float4 h = g_hf [n * 24 + lane];
            float4 a = g_agg[n * 24 + lane];
            float* tr = &tmp[w][s][q * 4];
            tr[0] = ea*h.x + a.x; tr[1] = ea*h.y + a.y;
            tr[2] = ea*h.z + a.z; tr[3] = ea*h.w + a.w;
        }
        __syncwarp();
        if (lane < 24)
            ar[w][lane] = 0.25f * (tmp[w][0][lane] + tmp[w][1][lane] +
                                   tmp[w][2][lane] + tmp[w][3][lane]);
        __syncwarp();
        u64 acc = b1p[lane];
#pragma unroll
        for (int j = 0; j < 24; j++) fma2(acc, w1p[j][lane], dup2(ar[w][j]));
        float lo, hi; unpack2(acc, lo, hi);
        hsm[w][lane]      = fmaxf(lo, 0.f);
        hsm[w][lane + 32] = fmaxf(hi, 0.f);
        __syncwarp();
        u64 o = b2p[lane];
#pragma unroll
        for (int k = 0; k < 64; k++) fma2(o, w2p[k][lane], dup2(hsm[w][k]));
        unpack2(o, lo, hi);
        g_ma[n * 64 + lane]      = lo;
        g_ma[n * 64 + lane + 32] = hi;
        __syncwarp();
    }
}

// ================= K5b: shared-path MLP + DSS combine -> out =====================
__global__ void __launch_bounds__(256) k_shared(const float* __restrict__ W2s,
                                                const float* __restrict__ b2s,
                                                const float* __restrict__ eps_s_p,
                                                float* __restrict__ out) {
    __shared__ u64 w1p[24][32];
    __shared__ u64 b1p[32];
    __shared__ u64 w2p[64][32];
    __shared__ u64 b2p[32];
    __shared__ float rows[8][4][24];
    __shared__ float hsm[8][64];
    int tid = threadIdx.x;
    for (int i = tid; i < 24 * 64; i += 256) {
        int j = i >> 6, l = i & 63;
        ((float*)&w1p[j][l & 31])[l >> 5] = g_W1f[0][i];
    }
    for (int i = tid; i < 64 * 64; i += 256) {
        int k = i >> 6, l = i & 63;
        ((float*)&w2p[k][l & 31])[l >> 5] = W2s[i];
    }
    if (tid < 64) {
        ((float*)&b1p[tid & 31])[tid >> 5] = g_b1f[0][tid];
        ((float*)&b2p[tid & 31])[tid >> 5] = b2s[tid];
    }
    float es = 1.f + *eps_s_p;
    __syncthreads();
    int w = tid >> 5, lane = tid & 31;
    for (int n = blockIdx.x * 8 + w; n < N_NODES; n += gridDim.x * 8) {
        __syncwarp();
        if (lane < 24) {
            int s = lane / 6, q = lane % 6;
            float4 h = g_hf [n * 24 + lane];
            float4 a = g_agg[n * 24 + lane];
            float* mr = &rows[w][s][q * 4];
            mr[0] = es*h.x + a.x; mr[1] = es*h.y + a.y;
            mr[2] = es*h.z + a.z; mr[3] = es*h.w + a.w;
        }
        float ma_lo = g_ma[n * 64 + lane];
        float ma_hi = g_ma[n * 64 + lane + 32];
        __syncwarp();
#pragma unroll
        for (int s = 0; s < 4; s++) {
            u64 acc = b1p[lane];
#pragma unroll
            for (int j = 0; j < 24; j++) fma2(acc, w1p[j][lane], dup2(rows[w][s][j]));
            float lo, hi; unpack2(acc, lo, hi);
            hsm[w][lane]      = fmaxf(lo, 0.f);
            hsm[w][lane + 32] = fmaxf(hi, 0.f);
            __syncwarp();
            u64 o = b2p[lane];
#pragma unroll
            for (int k = 0; k < 64; k++) fma2(o, w2p[k][lane], dup2(hsm[w][k]));
            unpack2(o, lo, hi);
            out[n * 256 + s * 64 + lane]      = lo + ma_lo;
            out[n * 256 + s * 64 + lane + 32] = hi + ma_hi;
            __syncwarp();
        }
    }
}

// ================= launch ========================================================
extern "C" void kernel_launch(void* const* d_in, const int* in_sizes, int n_in,
                              void* d_out, int out_size) {
    const float* x     = (const float*)d_in[0];
    const float* c     = (const float*)d_in[1];
    const int*   ei    = (const int*)  d_in[2];
    const float* eps_s = (const float*)d_in[3];
    const float* W1s   = (const float*)d_in[4];
    const float* b1s   = (const float*)d_in[5];
    const float* g1s   = (const float*)d_in[6];
    const float* be1s  = (const float*)d_in[7];
    const float* W2s   = (const float*)d_in[8];
    const float* b2s   = (const float*)d_in[9];
    const float* eps_a = (const float*)d_in[10];
    const float* W1a   = (const float*)d_in[11];
    const float* b1a   = (const float*)d_in[12];
    const float* g1a   = (const float*)d_in[13];
    const float* be1a  = (const float*)d_in[14];
    const float* W2a   = (const float*)d_in[15];
    const float* b2a   = (const float*)d_in[16];
    float* out = (float*)d_out;

    k_build<<<(NS + 255) / 256, 256>>>(x, c);
    k_scatter<<<(N_EDGES * 8 + 255) / 256, 256>>>(ei);
    k_stats<<<(N_NODES + 31) / 32, 128>>>(eps_s, eps_a);
    k_fold<<<1, 128>>>(W1s, b1s, g1s, be1s, W1a, b1a, g1a, be1a);
    k_agg<<<592, 256>>>(W2a, b2a, eps_a);
    k_shared<<<592, 256>>>(W2s, b2s, eps_s, out);
}